// round 3
// baseline (speedup 1.0000x reference)
#include <cuda_runtime.h>
#include <math.h>

#define B_    32
#define N_    512
#define H_    8
#define HID_  64
#define ACT_  4
#define ALPHA_ 0.2f

// ---------------- device scratch (no runtime allocs allowed) ----------------
__device__ float g_Wh  [B_*H_*N_*HID_];   // [b][h][n][o]
__device__ float g_ssrc[B_*H_*N_];
__device__ float g_sdst[B_*H_*N_];
__device__ float g_x   [B_*N_*H_*HID_];   // [b][n][h*64+o]
__device__ float g_Wh2 [B_*N_*64];
__device__ float g_s2s [B_*N_];
__device__ float g_s2d [B_*N_];
__device__ float g_h2  [B_*N_*64];        // z (B, 32768)
__device__ float g_z1p [32*B_*256];       // fc1 split-K partials

// =====================================================================
// 128-row x 64-col GEMM tile + per-row dots with aSrc/aDst.
// A row-major (B*N rows, K cols). Bmat = Ball + h*K*64, row-major KxN.
// =====================================================================
__global__ void gemm_s_kernel(const float* __restrict__ A,
                              const float* __restrict__ Ball,
                              const float* __restrict__ aSrc,
                              const float* __restrict__ aDst,
                              float* __restrict__ Cout,
                              float* __restrict__ sSrc,
                              float* __restrict__ sDst,
                              int K, int outBatch, int outHead, int sBatch)
{
    __shared__ float As[128*64];
    __shared__ float Bs[64*64];

    int tid = threadIdx.x;               // 256
    int r0  = blockIdx.x * 128;
    int h   = blockIdx.y;
    int b   = r0 / N_;
    int n0  = r0 % N_;
    const float* Bmat = Ball + (size_t)h*K*64;

    int tr = tid >> 4;   // 0..15 -> rows tr*8..+7
    int tc = tid & 15;   // 0..15 -> cols tc*4..+3

    float acc[8][4];
#pragma unroll
    for (int i = 0; i < 8; i++) { acc[i][0]=0.f; acc[i][1]=0.f; acc[i][2]=0.f; acc[i][3]=0.f; }

    for (int k0 = 0; k0 < K; k0 += 64) {
#pragma unroll
        for (int t = 0; t < 32; t++) {
            int lin = t*256 + tid;
            int row = lin >> 6, kk = lin & 63;
            As[row*64 + kk] = A[(size_t)(r0+row)*K + k0 + kk];
        }
#pragma unroll
        for (int t = 0; t < 16; t++) {
            int lin = t*256 + tid;
            int kk = lin >> 6, o = lin & 63;
            Bs[kk*64 + o] = Bmat[(size_t)(k0+kk)*64 + o];
        }
        __syncthreads();
#pragma unroll 8
        for (int k = 0; k < 64; k++) {
            float4 b4 = *(const float4*)&Bs[k*64 + tc*4];
#pragma unroll
            for (int i = 0; i < 8; i++) {
                float a = As[(tr*8+i)*64 + k];
                acc[i][0] += a*b4.x; acc[i][1] += a*b4.y;
                acc[i][2] += a*b4.z; acc[i][3] += a*b4.w;
            }
        }
        __syncthreads();
    }

    // write C
    float* outP = Cout + (size_t)b*outBatch + (size_t)h*outHead + (size_t)n0*64;
#pragma unroll
    for (int i = 0; i < 8; i++) {
        int row = tr*8 + i;
        float4 v = make_float4(acc[i][0], acc[i][1], acc[i][2], acc[i][3]);
        *(float4*)&outP[(size_t)row*64 + tc*4] = v;
    }

    // per-row dots: partial over this thread's 4 cols, reduce across 16 tc lanes
    const float* aS = aSrc + (size_t)h*64;
    const float* aD = aDst + (size_t)h*64;
    float a0 = __ldg(&aS[tc*4+0]), a1 = __ldg(&aS[tc*4+1]);
    float a2 = __ldg(&aS[tc*4+2]), a3 = __ldg(&aS[tc*4+3]);
    float d0 = __ldg(&aD[tc*4+0]), d1 = __ldg(&aD[tc*4+1]);
    float d2 = __ldg(&aD[tc*4+2]), d3 = __ldg(&aD[tc*4+3]);
#pragma unroll
    for (int i = 0; i < 8; i++) {
        float ss = acc[i][0]*a0 + acc[i][1]*a1 + acc[i][2]*a2 + acc[i][3]*a3;
        float sd = acc[i][0]*d0 + acc[i][1]*d1 + acc[i][2]*d2 + acc[i][3]*d3;
#pragma unroll
        for (int off = 8; off > 0; off >>= 1) {
            ss += __shfl_down_sync(0xffffffffu, ss, off, 16);
            sd += __shfl_down_sync(0xffffffffu, sd, off, 16);
        }
        if (tc == 0) {
            int n = n0 + tr*8 + i;
            sSrc[(size_t)b*sBatch + (size_t)h*N_ + n] = ss;
            sDst[(size_t)b*sBatch + (size_t)h*N_ + n] = sd;
        }
    }
}

// =====================================================================
// Sorted-prefix GAT attend. One block (512 thr) per (b,h).
// out[i,o] = (A*(TotP - PreP[k_i]) + B*PreQ[k_i]) / (same with Wh=1)
// =====================================================================
struct AttSmem {
    float Whp[512*64];
    float sd[512], ss[512], p[512], q[512];
    float cP[65*64], cQ[65*64];
    float spP[65], spQ[65];
    int   perm[512], kq[512];
};

__global__ void attend_kernel(const float* __restrict__ Wh,
                              const float* __restrict__ sS,
                              const float* __restrict__ sD,
                              float* __restrict__ out,
                              int outBatch, int outHead, int rowStride,
                              int hPerB, int applyElu)
{
    extern __shared__ char smraw[];
    AttSmem& s = *reinterpret_cast<AttSmem*>(smraw);
    int tid = threadIdx.x;                 // 512
    int g = blockIdx.x;
    int b = g / hPerB, h = g % hPerB;
    const float* WhG = Wh + (size_t)g*512*64;

    s.sd[tid]   = sD[(size_t)g*512 + tid];
    s.ss[tid]   = sS[(size_t)g*512 + tid];
    s.perm[tid] = tid;
    __syncthreads();

    // bitonic sort ascending by sd, carrying perm
    for (int k = 2; k <= 512; k <<= 1) {
        for (int j = k >> 1; j > 0; j >>= 1) {
            int ixj = tid ^ j;
            if (ixj > tid) {
                float v1 = s.sd[tid], v2 = s.sd[ixj];
                bool asc = (tid & k) == 0;
                if (asc ? (v1 > v2) : (v1 < v2)) {
                    s.sd[tid] = v2; s.sd[ixj] = v1;
                    int t1 = s.perm[tid]; s.perm[tid] = s.perm[ixj]; s.perm[ixj] = t1;
                }
            }
            __syncthreads();
        }
    }
    float dmax = s.sd[511];
    {
        float d = s.sd[tid] - dmax;
        s.p[tid] = expf(d);
        s.q[tid] = expf(ALPHA_ * d);
    }
    {   // k_i = upper_bound(sd, -s_i)
        float key = -s.ss[tid];
        int lo = 0, hi = 512;
        while (lo < hi) { int mid = (lo+hi) >> 1; if (s.sd[mid] <= key) lo = mid+1; else hi = mid; }
        s.kq[tid] = lo;
    }
    int grp = tid >> 6, lane = tid & 63;
    for (int j = grp; j < 512; j += 8)
        s.Whp[j*64 + lane] = WhG[(size_t)s.perm[j]*64 + lane];
    __syncthreads();

    // chunk sums over chunks of 8
    for (int c = grp; c < 64; c += 8) {
        float aP = 0.f, aQ = 0.f;
#pragma unroll
        for (int t = 0; t < 8; t++) {
            float w = s.Whp[(c*8+t)*64 + lane];
            aP += s.p[c*8+t] * w;
            aQ += s.q[c*8+t] * w;
        }
        s.cP[c*64 + lane] = aP;
        s.cQ[c*64 + lane] = aQ;
        if (lane == 0) {
            float bP = 0.f, bQ = 0.f;
#pragma unroll
            for (int t = 0; t < 8; t++) { bP += s.p[c*8+t]; bQ += s.q[c*8+t]; }
            s.spP[c] = bP; s.spQ[c] = bQ;
        }
    }
    __syncthreads();

    // exclusive prefix over 64 chunks
    if (tid < 64) {
        float rP = 0.f, rQ = 0.f;
        for (int c = 0; c < 64; c++) {
            float tP = s.cP[c*64 + tid]; s.cP[c*64 + tid] = rP; rP += tP;
            float tQ = s.cQ[c*64 + tid]; s.cQ[c*64 + tid] = rQ; rQ += tQ;
        }
        s.cP[64*64 + tid] = rP;
        s.cQ[64*64 + tid] = rQ;
    } else if (tid == 64) {
        float rP = 0.f, rQ = 0.f;
        for (int c = 0; c < 64; c++) {
            float tP = s.spP[c]; s.spP[c] = rP; rP += tP;
            float tQ = s.spQ[c]; s.spQ[c] = rQ; rQ += tQ;
        }
        s.spP[64] = rP; s.spQ[64] = rQ;
    }
    __syncthreads();

    float totSP = s.spP[64];
    float totPv = s.cP[64*64 + lane];
    float* outRow = out + (size_t)b*outBatch + (size_t)h*outHead;

    for (int it = 0; it < 64; it++) {
        int i = it*8 + grp;
        float sv = s.ss[i];
        int kk = s.kq[i];
        int c = kk >> 3;
        float vP = s.cP[c*64 + lane], vQ = s.cQ[c*64 + lane];
        float sp = s.spP[c],          sq = s.spQ[c];
        for (int t = c*8; t < kk; t++) {
            float w = s.Whp[t*64 + lane];
            float pp = s.p[t], qq = s.q[t];
            vP += pp*w; vQ += qq*w; sp += pp; sq += qq;
        }
        float spd = sv + dmax;
        float m   = spd > 0.f ? spd : ALPHA_*spd;
        float Af  = expf(spd - m);
        float Bf  = expf(ALPHA_*spd - m);
        float Z   = Af*(totSP - sp) + Bf*sq;
        float val = (Af*(totPv - vP) + Bf*vQ) / Z;
        if (applyElu) val = val > 0.f ? val : expm1f(val);
        outRow[(size_t)i*rowStride + lane] = val;
    }
}

// =====================================================================
// fc1 split-K: z (32 x 32768) @ W (32768 x 256). grid(4 col-tiles, 32 K-splits)
// =====================================================================
__global__ void fc1_kernel(const float* __restrict__ W)
{
    __shared__ float z_s[32*40];
    int tid = threadIdx.x;       // 256
    int cb = blockIdx.x;         // 0..3
    int ks = blockIdx.y;         // 0..31
    int rg = tid >> 5;           // 0..7 -> rows rg*4..+3
    int cl = tid & 31;
    int c0 = cb*64 + cl*2;
    int kbase = ks*1024;

    float acc[4][2];
#pragma unroll
    for (int i = 0; i < 4; i++) { acc[i][0]=0.f; acc[i][1]=0.f; }

    for (int kk = 0; kk < 1024; kk += 32) {
#pragma unroll
        for (int t = 0; t < 4; t++) {
            int lin = t*256 + tid;
            int row = lin >> 5, k2 = lin & 31;
            z_s[row*40 + k2] = g_h2[(size_t)row*32768 + kbase + kk + k2];
        }
        __syncthreads();
#pragma unroll
        for (int k2 = 0; k2 < 32; k2 += 4) {
            float4 zr[4];
#pragma unroll
            for (int i = 0; i < 4; i++)
                zr[i] = *(const float4*)&z_s[(rg*4+i)*40 + k2];
#pragma unroll
            for (int u = 0; u < 4; u++) {
                float2 w = *(const float2*)&W[(size_t)(kbase+kk+k2+u)*256 + c0];
#pragma unroll
                for (int i = 0; i < 4; i++) {
                    float zz = (u==0) ? zr[i].x : (u==1) ? zr[i].y : (u==2) ? zr[i].z : zr[i].w;
                    acc[i][0] += zz * w.x;
                    acc[i][1] += zz * w.y;
                }
            }
        }
        __syncthreads();
    }
#pragma unroll
    for (int i = 0; i < 4; i++) {
        g_z1p[(size_t)ks*8192 + (rg*4+i)*256 + c0 + 0] = acc[i][0];
        g_z1p[(size_t)ks*8192 + (rg*4+i)*256 + c0 + 1] = acc[i][1];
    }
}

// =====================================================================
// head: reduce fc1 partials + bias + relu -> fc2 relu -> fc3 tanh
// =====================================================================
__global__ void head_kernel(const float* __restrict__ fc1_b,
                            const float* __restrict__ fc2_w,
                            const float* __restrict__ fc2_b,
                            const float* __restrict__ fc3_w,
                            const float* __restrict__ fc3_b,
                            float* __restrict__ out)
{
    __shared__ float z2[256], z3[256];
    int b = blockIdx.x, t = threadIdx.x;
    float v = fc1_b[t];
#pragma unroll
    for (int ks = 0; ks < 32; ks++) v += g_z1p[(size_t)ks*8192 + b*256 + t];
    z2[t] = v > 0.f ? v : 0.f;
    __syncthreads();
    float y = fc2_b[t];
#pragma unroll 8
    for (int k = 0; k < 256; k++) y += z2[k] * fc2_w[(size_t)k*256 + t];
    z3[t] = y > 0.f ? y : 0.f;
    __syncthreads();
    if (t < ACT_) {
        float a = fc3_b[t];
        for (int k = 0; k < 256; k++) a += z3[k] * fc3_w[k*ACT_ + t];
        out[b*ACT_ + t] = tanhf(a);
    }
}

// =====================================================================
extern "C" void kernel_launch(void* const* d_in, const int* in_sizes, int n_in,
                              void* d_out, int out_size)
{
    (void)in_sizes; (void)n_in; (void)out_size;
    const float* state     = (const float*)d_in[0];
    const float* W_heads   = (const float*)d_in[1];
    const float* a_src     = (const float*)d_in[2];
    const float* a_dst     = (const float*)d_in[3];
    const float* W_out     = (const float*)d_in[4];
    const float* a_out_src = (const float*)d_in[5];
    const float* a_out_dst = (const float*)d_in[6];
    const float* fc1_w     = (const float*)d_in[7];
    const float* fc1_b     = (const float*)d_in[8];
    const float* fc2_w     = (const float*)d_in[9];
    const float* fc2_b     = (const float*)d_in[10];
    const float* fc3_w     = (const float*)d_in[11];
    const float* fc3_b     = (const float*)d_in[12];
    float* out = (float*)d_out;

    float *pWh, *pss, *psd, *px, *pWh2, *ps2s, *ps2d, *ph2;
    cudaGetSymbolAddress((void**)&pWh,  g_Wh);
    cudaGetSymbolAddress((void**)&pss,  g_ssrc);
    cudaGetSymbolAddress((void**)&psd,  g_sdst);
    cudaGetSymbolAddress((void**)&px,   g_x);
    cudaGetSymbolAddress((void**)&pWh2, g_Wh2);
    cudaGetSymbolAddress((void**)&ps2s, g_s2s);
    cudaGetSymbolAddress((void**)&ps2d, g_s2d);
    cudaGetSymbolAddress((void**)&ph2,  g_h2);

    int attSmem = (int)sizeof(AttSmem);
    cudaFuncSetAttribute(attend_kernel, cudaFuncAttributeMaxDynamicSharedMemorySize, attSmem);

    // Layer 1 GEMM: feat(B*N,64) @ W_heads(h)(64,64) -> Wh[b][h][n][o], s_src/s_dst
    gemm_s_kernel<<<dim3(128, 8), 256>>>(state, W_heads, a_src, a_dst,
                                         pWh, pss, psd,
                                         64, H_*N_*64, N_*64, H_*N_);
    // Attend 1 + ELU -> g_x[b][n][h*64+o]
    attend_kernel<<<256, 512, attSmem>>>(pWh, pss, psd, px,
                                         N_*H_*64, 64, H_*64, H_, 1);
    // Layer 2 GEMM: x(B*N,512) @ W_out(512,64) -> Wh2, s2
    gemm_s_kernel<<<dim3(128, 1), 256>>>(px, W_out, a_out_src, a_out_dst,
                                         pWh2, ps2s, ps2d,
                                         512, N_*64, 0, N_);
    // Attend 2 -> g_h2[b][n][o]
    attend_kernel<<<32, 512, attSmem>>>(pWh2, ps2s, ps2d, ph2,
                                        N_*64, 0, 64, 1, 0);
    // fc1 split-K partials
    fc1_kernel<<<dim3(4, 32), 256>>>(fc1_w);
    // reduce + fc2 + fc3 + tanh
    head_kernel<<<32, 256>>>(fc1_b, fc2_w, fc2_b, fc3_w, fc3_b, out);
}

// round 5
// speedup vs baseline: 1.1378x; 1.1378x over previous
#include <cuda_runtime.h>
#include <cuda_fp16.h>
#include <math.h>

#define B_    32
#define N_    512
#define H_    8
#define ACT_  4
#define ALPHA_ 0.2f

typedef unsigned long long ull;

// ---- packed f32x2 helpers (sm_100+) ----
__device__ __forceinline__ ull ffma2(ull a, ull b, ull c) {
    ull d; asm("fma.rn.f32x2 %0, %1, %2, %3;" : "=l"(d) : "l"(a), "l"(b), "l"(c)); return d;
}
__device__ __forceinline__ ull pack2(float lo, float hi) {
    ull r; asm("mov.b64 %0, {%1,%2};" : "=l"(r) : "f"(lo), "f"(hi)); return r;
}
__device__ __forceinline__ float pair_sum(ull v) {
    float lo, hi; asm("mov.b64 {%0,%1}, %2;" : "=f"(lo), "=f"(hi) : "l"(v)); return lo + hi;
}

// ---------------- device scratch ----------------
__device__ float g_Wh  [B_*H_*N_*64];
__device__ float g_ssrc[B_*H_*N_];
__device__ float g_sdst[B_*H_*N_];
__device__ float g_x   [B_*N_*H_*64];
__device__ float g_Wh2 [B_*N_*64];
__device__ float g_s2s [B_*N_];
__device__ float g_s2d [B_*N_];
__device__ float g_h2  [B_*N_*64];
__device__ float g_z1p [32*B_*256];

// =====================================================================
// GEMM 128x64 tile, K-pair packed ffma2, + per-row dots with aSrc/aDst.
// =====================================================================
__global__ void gemm_s_kernel(const float* __restrict__ A,
                              const float* __restrict__ Ball,
                              const float* __restrict__ aSrc,
                              const float* __restrict__ aDst,
                              float* __restrict__ Cout,
                              float* __restrict__ sSrc,
                              float* __restrict__ sDst,
                              int K, int outBatch, int outHead, int sBatch)
{
    __shared__ float As[128*64];      // [row][k], k contiguous per 64-tile
    __shared__ float Bst[64*66];      // [col][k] transposed, pad 66

    int tid = threadIdx.x;            // 256
    int r0  = blockIdx.x * 128;
    int h   = blockIdx.y;
    int b   = r0 / N_;
    int n0  = r0 % N_;
    const float* Bmat = Ball + (size_t)h*K*64;

    int tr = tid >> 4;   // 0..15 -> rows tr*8..+7
    int tc = tid & 15;   // cols tc, tc+16, tc+32, tc+48

    ull acc[8][4];
#pragma unroll
    for (int i = 0; i < 8; i++)
#pragma unroll
        for (int j = 0; j < 4; j++) acc[i][j] = 0ull;

    for (int k0 = 0; k0 < K; k0 += 64) {
#pragma unroll
        for (int t = 0; t < 32; t++) {
            int lin = t*256 + tid;
            int row = lin >> 6, kk = lin & 63;
            As[row*64 + kk] = A[(size_t)(r0+row)*K + k0 + kk];
        }
#pragma unroll
        for (int t = 0; t < 16; t++) {
            int lin = t*256 + tid;
            int kk = lin >> 6, o = lin & 63;
            Bst[o*66 + kk] = Bmat[(size_t)(k0+kk)*64 + o];
        }
        __syncthreads();
#pragma unroll 2
        for (int kp = 0; kp < 32; kp++) {
            ull bb0 = *(const ull*)&Bst[(tc     )*66 + 2*kp];
            ull bb1 = *(const ull*)&Bst[(tc + 16)*66 + 2*kp];
            ull bb2 = *(const ull*)&Bst[(tc + 32)*66 + 2*kp];
            ull bb3 = *(const ull*)&Bst[(tc + 48)*66 + 2*kp];
#pragma unroll
            for (int i = 0; i < 8; i++) {
                ull aa = *(const ull*)&As[(tr*8+i)*64 + 2*kp];
                acc[i][0] = ffma2(aa, bb0, acc[i][0]);
                acc[i][1] = ffma2(aa, bb1, acc[i][1]);
                acc[i][2] = ffma2(aa, bb2, acc[i][2]);
                acc[i][3] = ffma2(aa, bb3, acc[i][3]);
            }
        }
        __syncthreads();
    }

    float c[8][4];
#pragma unroll
    for (int i = 0; i < 8; i++)
#pragma unroll
        for (int j = 0; j < 4; j++) c[i][j] = pair_sum(acc[i][j]);

    float* outP = Cout + (size_t)b*outBatch + (size_t)h*outHead + (size_t)n0*64;
#pragma unroll
    for (int i = 0; i < 8; i++) {
        int row = tr*8 + i;
        outP[(size_t)row*64 + tc     ] = c[i][0];
        outP[(size_t)row*64 + tc + 16] = c[i][1];
        outP[(size_t)row*64 + tc + 32] = c[i][2];
        outP[(size_t)row*64 + tc + 48] = c[i][3];
    }

    const float* aS = aSrc + (size_t)h*64;
    const float* aD = aDst + (size_t)h*64;
    float aSv[4], aDv[4];
#pragma unroll
    for (int j = 0; j < 4; j++) {
        aSv[j] = __ldg(&aS[tc + 16*j]);
        aDv[j] = __ldg(&aD[tc + 16*j]);
    }
#pragma unroll
    for (int i = 0; i < 8; i++) {
        float ss = c[i][0]*aSv[0] + c[i][1]*aSv[1] + c[i][2]*aSv[2] + c[i][3]*aSv[3];
        float sd = c[i][0]*aDv[0] + c[i][1]*aDv[1] + c[i][2]*aDv[2] + c[i][3]*aDv[3];
#pragma unroll
        for (int off = 8; off > 0; off >>= 1) {
            ss += __shfl_down_sync(0xffffffffu, ss, off, 16);
            sd += __shfl_down_sync(0xffffffffu, sd, off, 16);
        }
        if (tc == 0) {
            int n = n0 + tr*8 + i;
            sSrc[(size_t)b*sBatch + (size_t)h*N_ + n] = ss;
            sDst[(size_t)b*sBatch + (size_t)h*N_ + n] = sd;
        }
    }
}

// =====================================================================
// Sorted-prefix GAT attend, v2: register bitonic sort (shfl for j<=16),
// exact scalar prefix via warp scans, chunk-16 vector prefix, fp16 Whp.
// =====================================================================
struct AttSmem {
    __half Whp[512*64];                 // 64 KB
    float sdp[512], ss[512], p[512], q[512], Pp[512], Pq[512];
    float cP[33*64], cQ[33*64];
    float wtP[16], wtQ[16];
    int   perm[512], kq[512];
};

__global__ void attend_kernel(const float* __restrict__ Wh,
                              const float* __restrict__ sS,
                              const float* __restrict__ sD,
                              float* __restrict__ out,
                              int outBatch, int outHead, int rowStride,
                              int hPerB, int applyElu)
{
    extern __shared__ char smraw[];
    AttSmem& s = *reinterpret_cast<AttSmem*>(smraw);
    int tid  = threadIdx.x;            // 512
    int lane = tid & 31, wid = tid >> 5;
    int g = blockIdx.x;
    int b = g / hPerB, h = g % hPerB;
    const float* WhG = Wh + (size_t)g*512*64;

    float key = sD[(size_t)g*512 + tid];
    int   val = tid;
    s.ss[tid] = sS[(size_t)g*512 + tid];

    // ---- bitonic sort ascending: regs, shfl for j<=16, smem for j>=32 ----
    for (int k = 2; k <= 512; k <<= 1) {
        int j = k >> 1;
        for (; j >= 32; j >>= 1) {
            s.sdp[tid] = key; s.perm[tid] = val;
            __syncthreads();
            float ok = s.sdp[tid ^ j];
            int   ov = s.perm[tid ^ j];
            __syncthreads();
            bool keepMin = ((tid & k) == 0) == ((tid & j) == 0);
            bool take = keepMin ? (ok < key) : (ok > key);
            if (take) { key = ok; val = ov; }
        }
        for (; j >= 1; j >>= 1) {
            float ok = __shfl_xor_sync(0xffffffffu, key, j);
            int   ov = __shfl_xor_sync(0xffffffffu, val, j);
            bool keepMin = ((tid & k) == 0) == ((tid & j) == 0);
            bool take = keepMin ? (ok < key) : (ok > key);
            if (take) { key = ok; val = ov; }
        }
    }
    s.sdp[tid] = key; s.perm[tid] = val;
    __syncthreads();

    float dmax = s.sdp[511];
    float pv = __expf(key - dmax);
    float qv = __expf(ALPHA_ * (key - dmax));
    s.p[tid] = pv; s.q[tid] = qv;

    // exact inclusive scalar scans of p, q over 512
    float ip = pv, iq = qv;
#pragma unroll
    for (int off = 1; off < 32; off <<= 1) {
        float np = __shfl_up_sync(0xffffffffu, ip, off);
        float nq = __shfl_up_sync(0xffffffffu, iq, off);
        if (lane >= off) { ip += np; iq += nq; }
    }
    if (lane == 31) { s.wtP[wid] = ip; s.wtQ[wid] = iq; }
    __syncthreads();
    float offP = 0.f, offQ = 0.f;
    for (int w2 = 0; w2 < wid; w2++) { offP += s.wtP[w2]; offQ += s.wtQ[w2]; }
    s.Pp[tid] = ip + offP;
    s.Pq[tid] = iq + offQ;

    // split point k_i = upper_bound(sdp, -s_i)
    {
        float ky = -s.ss[tid];
        int lo = 0, hi = 512;
        while (lo < hi) { int mid = (lo+hi) >> 1; if (s.sdp[mid] <= ky) lo = mid+1; else hi = mid; }
        s.kq[tid] = lo;
    }

    // gather permuted Wh rows as fp16
    int grp = tid >> 6, lane64 = tid & 63;
    for (int j = grp; j < 512; j += 8)
        s.Whp[j*64 + lane64] = __float2half_rn(WhG[(size_t)s.perm[j]*64 + lane64]);
    __syncthreads();

    // chunk sums (chunk = 16)
    for (int c = grp; c < 32; c += 8) {
        float aP = 0.f, aQ = 0.f;
#pragma unroll
        for (int t = 0; t < 16; t++) {
            float w = __half2float(s.Whp[(c*16+t)*64 + lane64]);
            aP = fmaf(s.p[c*16+t], w, aP);
            aQ = fmaf(s.q[c*16+t], w, aQ);
        }
        s.cP[c*64 + lane64] = aP;
        s.cQ[c*64 + lane64] = aQ;
    }
    __syncthreads();

    // exclusive chunk scan per lane (64 lanes)
    if (tid < 64) {
        float rP = 0.f, rQ = 0.f;
        for (int c = 0; c < 32; c++) {
            float tP = s.cP[c*64 + tid]; s.cP[c*64 + tid] = rP; rP += tP;
            float tQ = s.cQ[c*64 + tid]; s.cQ[c*64 + tid] = rQ; rQ += tQ;
        }
        s.cP[32*64 + tid] = rP;
        s.cQ[32*64 + tid] = rQ;
    }
    __syncthreads();

    float totS  = s.Pp[511];
    float totPv = s.cP[32*64 + lane64];
    float* outRow = out + (size_t)b*outBatch + (size_t)h*outHead;

    for (int it = 0; it < 64; it++) {
        int i = it*8 + grp;
        int kk = s.kq[i];
        float sv = s.ss[i];
        int c = kk >> 4;
        float vP = s.cP[c*64 + lane64], vQ = s.cQ[c*64 + lane64];
        for (int t = c*16; t < kk; t++) {        // uniform per group -> no divergence
            float w = __half2float(s.Whp[t*64 + lane64]);
            vP = fmaf(s.p[t], w, vP);
            vQ = fmaf(s.q[t], w, vQ);
        }
        float spx = kk ? s.Pp[kk-1] : 0.f;
        float sqx = kk ? s.Pq[kk-1] : 0.f;
        float spd = sv + dmax;
        float m   = spd > 0.f ? spd : ALPHA_*spd;
        float Af  = __expf(spd - m);
        float Bf  = __expf(ALPHA_*spd - m);
        float Z   = Af*(totS - spx) + Bf*sqx;
        float valf = (Af*(totPv - vP) + Bf*vQ) / Z;
        if (applyElu) valf = valf > 0.f ? valf : expm1f(valf);
        outRow[(size_t)i*rowStride + lane64] = valf;
    }
}

// =====================================================================
// fc1 split-K with ffma2 k-pairs: z (32 x 32768) @ W (32768 x 256)
// =====================================================================
__global__ void fc1_kernel(const float* __restrict__ W)
{
    __shared__ float z_s[32*40];
    int tid = threadIdx.x;       // 256
    int cb = blockIdx.x;         // 0..3
    int ks = blockIdx.y;         // 0..31
    int rg = tid >> 5;           // rows rg*4..+3
    int cl = tid & 31;
    int c0 = cb*64 + cl*2;
    int kbase = ks*1024;

    ull a0[4], a1[4];
#pragma unroll
    for (int i = 0; i < 4; i++) { a0[i] = 0ull; a1[i] = 0ull; }

    for (int kk = 0; kk < 1024; kk += 32) {
#pragma unroll
        for (int t = 0; t < 4; t++) {
            int lin = t*256 + tid;
            int row = lin >> 5, k2 = lin & 31;
            z_s[row*40 + k2] = g_h2[(size_t)row*32768 + kbase + kk + k2];
        }
        __syncthreads();
#pragma unroll 4
        for (int kp = 0; kp < 16; kp++) {
            size_t k = (size_t)(kbase + kk + 2*kp);
            float2 w0 = *(const float2*)&W[k*256 + c0];
            float2 w1 = *(const float2*)&W[(k+1)*256 + c0];
            ull wp0 = pack2(w0.x, w1.x);
            ull wp1 = pack2(w0.y, w1.y);
#pragma unroll
            for (int i = 0; i < 4; i++) {
                ull zz = *(const ull*)&z_s[(rg*4+i)*40 + 2*kp];
                a0[i] = ffma2(zz, wp0, a0[i]);
                a1[i] = ffma2(zz, wp1, a1[i]);
            }
        }
        __syncthreads();
    }
#pragma unroll
    for (int i = 0; i < 4; i++) {
        g_z1p[(size_t)ks*8192 + (rg*4+i)*256 + c0    ] = pair_sum(a0[i]);
        g_z1p[(size_t)ks*8192 + (rg*4+i)*256 + c0 + 1] = pair_sum(a1[i]);
    }
}

// =====================================================================
// head: reduce fc1 partials + relu -> fc2 relu -> fc3 tanh
// =====================================================================
__global__ void head_kernel(const float* __restrict__ fc1_b,
                            const float* __restrict__ fc2_w,
                            const float* __restrict__ fc2_b,
                            const float* __restrict__ fc3_w,
                            const float* __restrict__ fc3_b,
                            float* __restrict__ out)
{
    __shared__ float z2[256], z3[256];
    int b = blockIdx.x, t = threadIdx.x;
    float v = fc1_b[t];
#pragma unroll
    for (int ks = 0; ks < 32; ks++) v += g_z1p[(size_t)ks*8192 + b*256 + t];
    z2[t] = v > 0.f ? v : 0.f;
    __syncthreads();
    float y = fc2_b[t];
#pragma unroll 8
    for (int k = 0; k < 256; k++) y += z2[k] * fc2_w[(size_t)k*256 + t];
    z3[t] = y > 0.f ? y : 0.f;
    __syncthreads();
    if (t < ACT_) {
        float a = fc3_b[t];
        for (int k = 0; k < 256; k++) a += z3[k] * fc3_w[k*ACT_ + t];
        out[b*ACT_ + t] = tanhf(a);
    }
}

// =====================================================================
extern "C" void kernel_launch(void* const* d_in, const int* in_sizes, int n_in,
                              void* d_out, int out_size)
{
    (void)in_sizes; (void)n_in; (void)out_size;
    const float* state     = (const float*)d_in[0];
    const float* W_heads   = (const float*)d_in[1];
    const float* a_src     = (const float*)d_in[2];
    const float* a_dst     = (const float*)d_in[3];
    const float* W_out     = (const float*)d_in[4];
    const float* a_out_src = (const float*)d_in[5];
    const float* a_out_dst = (const float*)d_in[6];
    const float* fc1_w     = (const float*)d_in[7];
    const float* fc1_b     = (const float*)d_in[8];
    const float* fc2_w     = (const float*)d_in[9];
    const float* fc2_b     = (const float*)d_in[10];
    const float* fc3_w     = (const float*)d_in[11];
    const float* fc3_b     = (const float*)d_in[12];
    float* out = (float*)d_out;

    float *pWh, *pss, *psd, *px, *pWh2, *ps2s, *ps2d, *ph2;
    cudaGetSymbolAddress((void**)&pWh,  g_Wh);
    cudaGetSymbolAddress((void**)&pss,  g_ssrc);
    cudaGetSymbolAddress((void**)&psd,  g_sdst);
    cudaGetSymbolAddress((void**)&px,   g_x);
    cudaGetSymbolAddress((void**)&pWh2, g_Wh2);
    cudaGetSymbolAddress((void**)&ps2s, g_s2s);
    cudaGetSymbolAddress((void**)&ps2d, g_s2d);
    cudaGetSymbolAddress((void**)&ph2,  g_h2);

    int attSmem = (int)sizeof(AttSmem);
    static int attrDone = 0;
    if (!attrDone) {
        cudaFuncSetAttribute(attend_kernel, cudaFuncAttributeMaxDynamicSharedMemorySize, attSmem);
        attrDone = 1;
    }

    gemm_s_kernel<<<dim3(128, 8), 256>>>(state, W_heads, a_src, a_dst,
                                         pWh, pss, psd,
                                         64, H_*N_*64, N_*64, H_*N_);
    attend_kernel<<<256, 512, attSmem>>>(pWh, pss, psd, px,
                                         N_*H_*64, 64, H_*64, H_, 1);
    gemm_s_kernel<<<dim3(128, 1), 256>>>(px, W_out, a_out_src, a_out_dst,
                                         pWh2, ps2s, ps2d,
                                         512, N_*64, 0, N_);
    attend_kernel<<<32, 512, attSmem>>>(pWh2, ps2s, ps2d, ph2,
                                        N_*64, 0, 64, 1, 0);
    fc1_kernel<<<dim3(4, 32), 256>>>(fc1_w);
    head_kernel<<<32, 256>>>(fc1_b, fc2_w, fc2_b, fc3_w, fc3_b, out);
}

// round 8
// speedup vs baseline: 1.2570x; 1.1048x over previous
#include <cuda_runtime.h>
#include <cuda_fp16.h>
#include <math.h>

#define B_    32
#define N_    512
#define H_    8
#define ACT_  4
#define ALPHA_ 0.2f

typedef unsigned long long ull;

// ---- packed f32x2 helpers (sm_100+) ----
__device__ __forceinline__ ull ffma2(ull a, ull b, ull c) {
    ull d; asm("fma.rn.f32x2 %0, %1, %2, %3;" : "=l"(d) : "l"(a), "l"(b), "l"(c)); return d;
}
__device__ __forceinline__ ull add2(ull a, ull b) {
    ull d; asm("add.rn.f32x2 %0, %1, %2;" : "=l"(d) : "l"(a), "l"(b)); return d;
}
__device__ __forceinline__ ull pack2(float lo, float hi) {
    ull r; asm("mov.b64 %0, {%1,%2};" : "=l"(r) : "f"(lo), "f"(hi)); return r;
}
__device__ __forceinline__ void unpack2(ull v, float& lo, float& hi) {
    asm("mov.b64 {%0,%1}, %2;" : "=f"(lo), "=f"(hi) : "l"(v));
}
__device__ __forceinline__ float pair_sum(ull v) {
    float lo, hi; unpack2(v, lo, hi); return lo + hi;
}

// ---------------- device scratch ----------------
__device__ float g_Wh  [B_*H_*N_*64];
__device__ float g_ssrc[B_*H_*N_];
__device__ float g_sdst[B_*H_*N_];
__device__ float g_x   [B_*N_*H_*64];
__device__ float g_Wh2 [B_*N_*64];
__device__ float g_s2s [B_*N_];
__device__ float g_s2d [B_*N_];
__device__ float g_h2  [B_*N_*64];
__device__ float g_z1p [32*B_*256];

// =====================================================================
// GEMM 128x64 tile, LDS.128 k-quads + ffma2, + per-row dots aSrc/aDst.
// =====================================================================
__global__ void gemm_s_kernel(const float* __restrict__ A,
                              const float* __restrict__ Ball,
                              const float* __restrict__ aSrc,
                              const float* __restrict__ aDst,
                              float* __restrict__ Cout,
                              float* __restrict__ sSrc,
                              float* __restrict__ sDst,
                              int K, int outBatch, int outHead, int sBatch)
{
    __shared__ float As[128*64];      // [row][k]
    __shared__ float Bst[64*68];      // [col][k] transposed, stride 68 (16B-aligned)

    int tid = threadIdx.x;            // 256
    int r0  = blockIdx.x * 128;
    int h   = blockIdx.y;
    int b   = r0 / N_;
    int n0  = r0 % N_;
    const float* Bmat = Ball + (size_t)h*K*64;

    int tr = tid >> 4;   // 0..15 -> rows tr*8..+7
    int tc = tid & 15;   // cols tc, tc+16, tc+32, tc+48

    ull acc[8][4];
#pragma unroll
    for (int i = 0; i < 8; i++)
#pragma unroll
        for (int j = 0; j < 4; j++) acc[i][j] = 0ull;

    for (int k0 = 0; k0 < K; k0 += 64) {
#pragma unroll
        for (int t = 0; t < 32; t++) {
            int lin = t*256 + tid;
            int row = lin >> 6, kk = lin & 63;
            As[row*64 + kk] = A[(size_t)(r0+row)*K + k0 + kk];
        }
#pragma unroll
        for (int t = 0; t < 16; t++) {
            int lin = t*256 + tid;
            int kk = lin >> 6, o = lin & 63;
            Bst[o*68 + kk] = Bmat[(size_t)(k0+kk)*64 + o];
        }
        __syncthreads();
#pragma unroll 2
        for (int kq = 0; kq < 16; kq++) {       // 4 k per iter
            ulonglong2 b0 = *(const ulonglong2*)&Bst[(tc     )*68 + 4*kq];
            ulonglong2 b1 = *(const ulonglong2*)&Bst[(tc + 16)*68 + 4*kq];
            ulonglong2 b2 = *(const ulonglong2*)&Bst[(tc + 32)*68 + 4*kq];
            ulonglong2 b3 = *(const ulonglong2*)&Bst[(tc + 48)*68 + 4*kq];
#pragma unroll
            for (int i = 0; i < 8; i++) {
                ulonglong2 av = *(const ulonglong2*)&As[(tr*8+i)*64 + 4*kq];
                acc[i][0] = ffma2(av.x, b0.x, acc[i][0]);
                acc[i][1] = ffma2(av.x, b1.x, acc[i][1]);
                acc[i][2] = ffma2(av.x, b2.x, acc[i][2]);
                acc[i][3] = ffma2(av.x, b3.x, acc[i][3]);
                acc[i][0] = ffma2(av.y, b0.y, acc[i][0]);
                acc[i][1] = ffma2(av.y, b1.y, acc[i][1]);
                acc[i][2] = ffma2(av.y, b2.y, acc[i][2]);
                acc[i][3] = ffma2(av.y, b3.y, acc[i][3]);
            }
        }
        __syncthreads();
    }

    float c[8][4];
#pragma unroll
    for (int i = 0; i < 8; i++)
#pragma unroll
        for (int j = 0; j < 4; j++) c[i][j] = pair_sum(acc[i][j]);

    float* outP = Cout + (size_t)b*outBatch + (size_t)h*outHead + (size_t)n0*64;
#pragma unroll
    for (int i = 0; i < 8; i++) {
        int row = tr*8 + i;
        outP[(size_t)row*64 + tc     ] = c[i][0];
        outP[(size_t)row*64 + tc + 16] = c[i][1];
        outP[(size_t)row*64 + tc + 32] = c[i][2];
        outP[(size_t)row*64 + tc + 48] = c[i][3];
    }

    const float* aS = aSrc + (size_t)h*64;
    const float* aD = aDst + (size_t)h*64;
    float aSv[4], aDv[4];
#pragma unroll
    for (int j = 0; j < 4; j++) {
        aSv[j] = __ldg(&aS[tc + 16*j]);
        aDv[j] = __ldg(&aD[tc + 16*j]);
    }
#pragma unroll
    for (int i = 0; i < 8; i++) {
        float ss = c[i][0]*aSv[0] + c[i][1]*aSv[1] + c[i][2]*aSv[2] + c[i][3]*aSv[3];
        float sd = c[i][0]*aDv[0] + c[i][1]*aDv[1] + c[i][2]*aDv[2] + c[i][3]*aDv[3];
#pragma unroll
        for (int off = 8; off > 0; off >>= 1) {
            ss += __shfl_down_sync(0xffffffffu, ss, off, 16);
            sd += __shfl_down_sync(0xffffffffu, sd, off, 16);
        }
        if (tc == 0) {
            int n = n0 + tr*8 + i;
            sSrc[(size_t)b*sBatch + (size_t)h*N_ + n] = ss;
            sDst[(size_t)b*sBatch + (size_t)h*N_ + n] = sd;
        }
    }
}

// =====================================================================
// Sorted-prefix GAT attend v3: warp-per-query, f32x2 packed channel pairs.
// =====================================================================
struct AttSmem {
    __half2 Whp[512*32];               // 64 KB, [row][lanepair]
    ull cP2[33*32], cQ2[33*32];        // chunk prefix (chunk=16), 16.9 KB
    float sdp[512], ss[512], p[512], q[512], Pp[512], Pq[512];
    int   perm[512], kq[512];
    float wtP[16], wtQ[16];
};

__global__ void attend_kernel(const float* __restrict__ Wh,
                              const float* __restrict__ sS,
                              const float* __restrict__ sD,
                              float* __restrict__ out,
                              int outBatch, int outHead, int rowStride,
                              int hPerB, int applyElu)
{
    extern __shared__ char smraw[];
    AttSmem& s = *reinterpret_cast<AttSmem*>(smraw);
    int tid  = threadIdx.x;            // 512
    int lane = tid & 31, wid = tid >> 5;   // 16 warps
    int g = blockIdx.x;
    int b = g / hPerB, h = g % hPerB;
    const float* WhG = Wh + (size_t)g*512*64;

    float key = sD[(size_t)g*512 + tid];
    int   val = tid;
    s.ss[tid] = sS[(size_t)g*512 + tid];

    // ---- bitonic sort ascending: smem for j>=32, shfl for j<=16 ----
    for (int k = 2; k <= 512; k <<= 1) {
        int j = k >> 1;
        for (; j >= 32; j >>= 1) {
            s.sdp[tid] = key; s.perm[tid] = val;
            __syncthreads();
            float ok = s.sdp[tid ^ j];
            int   ov = s.perm[tid ^ j];
            __syncthreads();
            bool keepMin = ((tid & k) == 0) == ((tid & j) == 0);
            bool take = keepMin ? (ok < key) : (ok > key);
            if (take) { key = ok; val = ov; }
        }
        for (; j >= 1; j >>= 1) {
            float ok = __shfl_xor_sync(0xffffffffu, key, j);
            int   ov = __shfl_xor_sync(0xffffffffu, val, j);
            bool keepMin = ((tid & k) == 0) == ((tid & j) == 0);
            bool take = keepMin ? (ok < key) : (ok > key);
            if (take) { key = ok; val = ov; }
        }
    }
    s.sdp[tid] = key; s.perm[tid] = val;
    __syncthreads();

    float dmax = s.sdp[511];
    float pv = __expf(key - dmax);
    float qv = __expf(ALPHA_ * (key - dmax));
    s.p[tid] = pv; s.q[tid] = qv;

    // exact inclusive scans of p, q over 512 (warp scan + warp-total combine)
    float ip = pv, iq = qv;
#pragma unroll
    for (int off = 1; off < 32; off <<= 1) {
        float np = __shfl_up_sync(0xffffffffu, ip, off);
        float nq = __shfl_up_sync(0xffffffffu, iq, off);
        if (lane >= off) { ip += np; iq += nq; }
    }
    if (lane == 31) { s.wtP[wid] = ip; s.wtQ[wid] = iq; }
    __syncthreads();
    float offP = 0.f, offQ = 0.f;
    for (int w2 = 0; w2 < wid; w2++) { offP += s.wtP[w2]; offQ += s.wtQ[w2]; }
    s.Pp[tid] = ip + offP;
    s.Pq[tid] = iq + offQ;

    // split point k_i = upper_bound(sdp, -s_i)
    {
        float ky = -s.ss[tid];
        int lo = 0, hi = 512;
        while (lo < hi) { int mid = (lo+hi) >> 1; if (s.sdp[mid] <= ky) lo = mid+1; else hi = mid; }
        s.kq[tid] = lo;
    }

    // gather permuted Wh rows as half2 channel pairs
    for (int j = wid; j < 512; j += 16) {
        float2 v = *(const float2*)&WhG[(size_t)s.perm[j]*64 + 2*lane];
        s.Whp[j*32 + lane] = __floats2half2_rn(v.x, v.y);
    }
    __syncthreads();

    // chunk sums (chunk = 16): warp w does chunks 2w, 2w+1
#pragma unroll
    for (int cc = 0; cc < 2; cc++) {
        int c = wid*2 + cc;
        ull aP = 0ull, aQ = 0ull;
#pragma unroll
        for (int t = 0; t < 16; t++) {
            int row = c*16 + t;
            float2 wf = __half22float2(s.Whp[row*32 + lane]);
            ull w2 = pack2(wf.x, wf.y);
            float pt = s.p[row], qt = s.q[row];
            aP = ffma2(w2, pack2(pt, pt), aP);
            aQ = ffma2(w2, pack2(qt, qt), aQ);
        }
        s.cP2[c*32 + lane] = aP;
        s.cQ2[c*32 + lane] = aQ;
    }
    __syncthreads();

    // exclusive chunk scan per lane-pair (32 lanes)
    if (tid < 32) {
        ull rP = 0ull, rQ = 0ull;
        for (int c = 0; c < 32; c++) {
            ull tP = s.cP2[c*32 + tid]; s.cP2[c*32 + tid] = rP; rP = add2(rP, tP);
            ull tQ = s.cQ2[c*32 + tid]; s.cQ2[c*32 + tid] = rQ; rQ = add2(rQ, tQ);
        }
        s.cP2[32*32 + tid] = rP;
        s.cQ2[32*32 + tid] = rQ;
    }
    __syncthreads();

    float totS = s.Pp[511];
    float totPx, totPy; unpack2(s.cP2[32*32 + lane], totPx, totPy);
    float* outRow = out + (size_t)b*outBatch + (size_t)h*outHead;

    for (int it = 0; it < 32; it++) {
        int i = it*16 + wid;
        int kk = s.kq[i];
        float sv = s.ss[i];
        int c = kk >> 4;
        ull vP = s.cP2[c*32 + lane], vQ = s.cQ2[c*32 + lane];
        for (int t = c*16; t < kk; t++) {        // uniform across warp
            float2 wf = __half22float2(s.Whp[t*32 + lane]);
            ull w2 = pack2(wf.x, wf.y);
            float pt = s.p[t], qt = s.q[t];
            vP = ffma2(w2, pack2(pt, pt), vP);
            vQ = ffma2(w2, pack2(qt, qt), vQ);
        }
        float spx = kk ? s.Pp[kk-1] : 0.f;
        float sqx = kk ? s.Pq[kk-1] : 0.f;
        float spd = sv + dmax;
        float m   = spd > 0.f ? spd : ALPHA_*spd;
        float Af  = __expf(spd - m);
        float Bf  = __expf(ALPHA_*spd - m);
        float invZ = 1.f / (Af*(totS - spx) + Bf*sqx);
        float vPx, vPy, vQx, vQy;
        unpack2(vP, vPx, vPy); unpack2(vQ, vQx, vQy);
        float vx = (Af*(totPx - vPx) + Bf*vQx) * invZ;
        float vy = (Af*(totPy - vPy) + Bf*vQy) * invZ;
        if (applyElu) {
            vx = vx > 0.f ? vx : expm1f(vx);
            vy = vy > 0.f ? vy : expm1f(vy);
        }
        *(float2*)&outRow[(size_t)i*rowStride + 2*lane] = make_float2(vx, vy);
    }
}

// =====================================================================
// fc1 split-K with ffma2 k-pairs + LDS.128: z (32 x 32768) @ W (32768 x 256)
// =====================================================================
__global__ void fc1_kernel(const float* __restrict__ W)
{
    __shared__ float z_s[32*40];      // stride 40 floats = 160B, 16B-aligned
    int tid = threadIdx.x;       // 256
    int cb = blockIdx.x;         // 0..3
    int ks = blockIdx.y;         // 0..31
    int rg = tid >> 5;           // rows rg*4..+3
    int cl = tid & 31;
    int c0 = cb*64 + cl*2;
    int kbase = ks*1024;

    ull a0[4], a1[4];
#pragma unroll
    for (int i = 0; i < 4; i++) { a0[i] = 0ull; a1[i] = 0ull; }

    for (int kk = 0; kk < 1024; kk += 32) {
#pragma unroll
        for (int t = 0; t < 4; t++) {
            int lin = t*256 + tid;
            int row = lin >> 5, k2 = lin & 31;
            z_s[row*40 + k2] = g_h2[(size_t)row*32768 + kbase + kk + k2];
        }
        __syncthreads();
#pragma unroll 2
        for (int kq = 0; kq < 8; kq++) {        // 4 k per iter
            size_t k = (size_t)(kbase + kk + 4*kq);
            float2 w0 = *(const float2*)&W[ k     *256 + c0];
            float2 w1 = *(const float2*)&W[(k+1)*256 + c0];
            float2 w2 = *(const float2*)&W[(k+2)*256 + c0];
            float2 w3 = *(const float2*)&W[(k+3)*256 + c0];
            ull wa0 = pack2(w0.x, w1.x), wa1 = pack2(w2.x, w3.x);
            ull wb0 = pack2(w0.y, w1.y), wb1 = pack2(w2.y, w3.y);
#pragma unroll
            for (int i = 0; i < 4; i++) {
                ulonglong2 zz = *(const ulonglong2*)&z_s[(rg*4+i)*40 + 4*kq];
                a0[i] = ffma2(zz.x, wa0, a0[i]);
                a1[i] = ffma2(zz.x, wb0, a1[i]);
                a0[i] = ffma2(zz.y, wa1, a0[i]);
                a1[i] = ffma2(zz.y, wb1, a1[i]);
            }
        }
        __syncthreads();
    }
#pragma unroll
    for (int i = 0; i < 4; i++) {
        g_z1p[(size_t)ks*8192 + (rg*4+i)*256 + c0    ] = pair_sum(a0[i]);
        g_z1p[(size_t)ks*8192 + (rg*4+i)*256 + c0 + 1] = pair_sum(a1[i]);
    }
}

// =====================================================================
// head: reduce fc1 partials + relu -> fc2 relu -> fc3 tanh
// =====================================================================
__global__ void head_kernel(const float* __restrict__ fc1_b,
                            const float* __restrict__ fc2_w,
                            const float* __restrict__ fc2_b,
                            const float* __restrict__ fc3_w,
                            const float* __restrict__ fc3_b,
                            float* __restrict__ out)
{
    __shared__ float z2[256], z3[256];
    int b = blockIdx.x, t = threadIdx.x;
    float v = fc1_b[t];
#pragma unroll
    for (int ks = 0; ks < 32; ks++) v += g_z1p[(size_t)ks*8192 + b*256 + t];
    z2[t] = v > 0.f ? v : 0.f;
    __syncthreads();
    float y = fc2_b[t];
#pragma unroll 8
    for (int k = 0; k < 256; k++) y += z2[k] * fc2_w[(size_t)k*256 + t];
    z3[t] = y > 0.f ? y : 0.f;
    __syncthreads();
    if (t < ACT_) {
        float a = fc3_b[t];
        for (int k = 0; k < 256; k++) a += z3[k] * fc3_w[k*ACT_ + t];
        out[b*ACT_ + t] = tanhf(a);
    }
}

// =====================================================================
extern "C" void kernel_launch(void* const* d_in, const int* in_sizes, int n_in,
                              void* d_out, int out_size)
{
    (void)in_sizes; (void)n_in; (void)out_size;
    const float* state     = (const float*)d_in[0];
    const float* W_heads   = (const float*)d_in[1];
    const float* a_src     = (const float*)d_in[2];
    const float* a_dst     = (const float*)d_in[3];
    const float* W_out     = (const float*)d_in[4];
    const float* a_out_src = (const float*)d_in[5];
    const float* a_out_dst = (const float*)d_in[6];
    const float* fc1_w     = (const float*)d_in[7];
    const float* fc1_b     = (const float*)d_in[8];
    const float* fc2_w     = (const float*)d_in[9];
    const float* fc2_b     = (const float*)d_in[10];
    const float* fc3_w     = (const float*)d_in[11];
    const float* fc3_b     = (const float*)d_in[12];
    float* out = (float*)d_out;

    float *pWh, *pss, *psd, *px, *pWh2, *ps2s, *ps2d, *ph2;
    cudaGetSymbolAddress((void**)&pWh,  g_Wh);
    cudaGetSymbolAddress((void**)&pss,  g_ssrc);
    cudaGetSymbolAddress((void**)&psd,  g_sdst);
    cudaGetSymbolAddress((void**)&px,   g_x);
    cudaGetSymbolAddress((void**)&pWh2, g_Wh2);
    cudaGetSymbolAddress((void**)&ps2s, g_s2s);
    cudaGetSymbolAddress((void**)&ps2d, g_s2d);
    cudaGetSymbolAddress((void**)&ph2,  g_h2);

    int attSmem = (int)sizeof(AttSmem);
    cudaFuncSetAttribute(attend_kernel, cudaFuncAttributeMaxDynamicSharedMemorySize, attSmem);

    gemm_s_kernel<<<dim3(128, 8), 256>>>(state, W_heads, a_src, a_dst,
                                         pWh, pss, psd,
                                         64, H_*N_*64, N_*64, H_*N_);
    attend_kernel<<<256, 512, attSmem>>>(pWh, pss, psd, px,
                                         N_*H_*64, 64, H_*64, H_, 1);
    gemm_s_kernel<<<dim3(128, 1), 256>>>(px, W_out, a_out_src, a_out_dst,
                                         pWh2, ps2s, ps2d,
                                         512, N_*64, 0, N_);
    attend_kernel<<<32, 512, attSmem>>>(pWh2, ps2s, ps2d, ph2,
                                        N_*64, 0, 64, 1, 0);
    fc1_kernel<<<dim3(4, 32), 256>>>(fc1_w);
    head_kernel<<<32, 256>>>(fc1_b, fc2_w, fc2_b, fc3_w, fc3_b, out);
}

// round 10
// speedup vs baseline: 1.9176x; 1.5255x over previous
#include <cuda_runtime.h>
#include <cuda_fp16.h>
#include <math.h>

#define B_    32
#define N_    512
#define H_    8
#define ACT_  4
#define ALPHA_ 0.2f

typedef unsigned long long ull;

// ---- packed f32x2 helpers (sm_100+) ----
__device__ __forceinline__ ull ffma2(ull a, ull b, ull c) {
    ull d; asm("fma.rn.f32x2 %0, %1, %2, %3;" : "=l"(d) : "l"(a), "l"(b), "l"(c)); return d;
}
__device__ __forceinline__ ull add2(ull a, ull b) {
    ull d; asm("add.rn.f32x2 %0, %1, %2;" : "=l"(d) : "l"(a), "l"(b)); return d;
}
__device__ __forceinline__ ull pack2(float lo, float hi) {
    ull r; asm("mov.b64 %0, {%1,%2};" : "=l"(r) : "f"(lo), "f"(hi)); return r;
}
__device__ __forceinline__ void unpack2(ull v, float& lo, float& hi) {
    asm("mov.b64 {%0,%1}, %2;" : "=f"(lo), "=f"(hi) : "l"(v));
}
__device__ __forceinline__ float pair_sum(ull v) {
    float lo, hi; unpack2(v, lo, hi); return lo + hi;
}

// ---------------- device scratch ----------------
__device__ float g_Wh  [B_*H_*N_*64];
__device__ float g_ssrc[B_*H_*N_];
__device__ float g_sdst[B_*H_*N_];
__device__ float g_x   [B_*N_*H_*64];
__device__ float g_Wh2 [B_*N_*64];
__device__ float g_s2s [B_*N_];
__device__ float g_s2d [B_*N_];
__device__ float g_h2  [B_*N_*64];
__device__ float g_z1p [32*B_*256];

// =====================================================================
// GEMM 128x64 tile, LDS.128 k-quads + ffma2, + per-row dots aSrc/aDst.
// =====================================================================
__global__ void gemm_s_kernel(const float* __restrict__ A,
                              const float* __restrict__ Ball,
                              const float* __restrict__ aSrc,
                              const float* __restrict__ aDst,
                              float* __restrict__ Cout,
                              float* __restrict__ sSrc,
                              float* __restrict__ sDst,
                              int K, int outBatch, int outHead, int sBatch)
{
    __shared__ float As[128*64];
    __shared__ float Bst[64*68];

    int tid = threadIdx.x;            // 256
    int r0  = blockIdx.x * 128;
    int h   = blockIdx.y;
    int b   = r0 / N_;
    int n0  = r0 % N_;
    const float* Bmat = Ball + (size_t)h*K*64;

    int tr = tid >> 4;
    int tc = tid & 15;

    ull acc[8][4];
#pragma unroll
    for (int i = 0; i < 8; i++)
#pragma unroll
        for (int j = 0; j < 4; j++) acc[i][j] = 0ull;

    for (int k0 = 0; k0 < K; k0 += 64) {
#pragma unroll
        for (int t = 0; t < 32; t++) {
            int lin = t*256 + tid;
            int row = lin >> 6, kk = lin & 63;
            As[row*64 + kk] = A[(size_t)(r0+row)*K + k0 + kk];
        }
#pragma unroll
        for (int t = 0; t < 16; t++) {
            int lin = t*256 + tid;
            int kk = lin >> 6, o = lin & 63;
            Bst[o*68 + kk] = Bmat[(size_t)(k0+kk)*64 + o];
        }
        __syncthreads();
#pragma unroll 2
        for (int kq = 0; kq < 16; kq++) {
            ulonglong2 b0 = *(const ulonglong2*)&Bst[(tc     )*68 + 4*kq];
            ulonglong2 b1 = *(const ulonglong2*)&Bst[(tc + 16)*68 + 4*kq];
            ulonglong2 b2 = *(const ulonglong2*)&Bst[(tc + 32)*68 + 4*kq];
            ulonglong2 b3 = *(const ulonglong2*)&Bst[(tc + 48)*68 + 4*kq];
#pragma unroll
            for (int i = 0; i < 8; i++) {
                ulonglong2 av = *(const ulonglong2*)&As[(tr*8+i)*64 + 4*kq];
                acc[i][0] = ffma2(av.x, b0.x, acc[i][0]);
                acc[i][1] = ffma2(av.x, b1.x, acc[i][1]);
                acc[i][2] = ffma2(av.x, b2.x, acc[i][2]);
                acc[i][3] = ffma2(av.x, b3.x, acc[i][3]);
                acc[i][0] = ffma2(av.y, b0.y, acc[i][0]);
                acc[i][1] = ffma2(av.y, b1.y, acc[i][1]);
                acc[i][2] = ffma2(av.y, b2.y, acc[i][2]);
                acc[i][3] = ffma2(av.y, b3.y, acc[i][3]);
            }
        }
        __syncthreads();
    }

    float c[8][4];
#pragma unroll
    for (int i = 0; i < 8; i++)
#pragma unroll
        for (int j = 0; j < 4; j++) c[i][j] = pair_sum(acc[i][j]);

    float* outP = Cout + (size_t)b*outBatch + (size_t)h*outHead + (size_t)n0*64;
#pragma unroll
    for (int i = 0; i < 8; i++) {
        int row = tr*8 + i;
        outP[(size_t)row*64 + tc     ] = c[i][0];
        outP[(size_t)row*64 + tc + 16] = c[i][1];
        outP[(size_t)row*64 + tc + 32] = c[i][2];
        outP[(size_t)row*64 + tc + 48] = c[i][3];
    }

    const float* aS = aSrc + (size_t)h*64;
    const float* aD = aDst + (size_t)h*64;
    float aSv[4], aDv[4];
#pragma unroll
    for (int j = 0; j < 4; j++) {
        aSv[j] = __ldg(&aS[tc + 16*j]);
        aDv[j] = __ldg(&aD[tc + 16*j]);
    }
#pragma unroll
    for (int i = 0; i < 8; i++) {
        float ss = c[i][0]*aSv[0] + c[i][1]*aSv[1] + c[i][2]*aSv[2] + c[i][3]*aSv[3];
        float sd = c[i][0]*aDv[0] + c[i][1]*aDv[1] + c[i][2]*aDv[2] + c[i][3]*aDv[3];
#pragma unroll
        for (int off = 8; off > 0; off >>= 1) {
            ss += __shfl_down_sync(0xffffffffu, ss, off, 16);
            sd += __shfl_down_sync(0xffffffffu, sd, off, 16);
        }
        if (tc == 0) {
            int n = n0 + tr*8 + i;
            sSrc[(size_t)b*sBatch + (size_t)h*N_ + n] = ss;
            sDst[(size_t)b*sBatch + (size_t)h*N_ + n] = sd;
        }
    }
}

// =====================================================================
// Sorted-prefix GAT attend v4:
//  - packed p2/q2 smem (fewer tail instrs)
//  - bidirectional tails (avg 4 iters instead of 8)
//  - multi-warp Hillis-Steele chunk scan (no serial single-warp scan)
// =====================================================================
struct AttSmem {
    __half2 Whp[512*32];               // 64 KB
    ull p2[512], q2[512];              // 8 KB, pack2(p,p)/pack2(q,q)
    ull cP2[33*32], cQ2[33*32];        // 16.5 KB, exclusive chunk prefix, [32]=total
    float sdp[512], ss[512], Pp[512], Pq[512];
    int   perm[512], kq[512];
    float wtP[16], wtQ[16];
};

__global__ void attend_kernel(const float* __restrict__ Wh,
                              const float* __restrict__ sS,
                              const float* __restrict__ sD,
                              float* __restrict__ out,
                              int outBatch, int outHead, int rowStride,
                              int hPerB, int applyElu)
{
    extern __shared__ char smraw[];
    AttSmem& s = *reinterpret_cast<AttSmem*>(smraw);
    int tid  = threadIdx.x;            // 512
    int lane = tid & 31, wid = tid >> 5;   // 16 warps
    int g = blockIdx.x;
    int b = g / hPerB, h = g % hPerB;
    const float* WhG = Wh + (size_t)g*512*64;

    float key = sD[(size_t)g*512 + tid];
    int   val = tid;
    s.ss[tid] = sS[(size_t)g*512 + tid];

    // ---- bitonic sort ascending: smem for j>=32, shfl for j<=16 ----
    for (int k = 2; k <= 512; k <<= 1) {
        int j = k >> 1;
        for (; j >= 32; j >>= 1) {
            s.sdp[tid] = key; s.perm[tid] = val;
            __syncthreads();
            float ok = s.sdp[tid ^ j];
            int   ov = s.perm[tid ^ j];
            __syncthreads();
            bool keepMin = ((tid & k) == 0) == ((tid & j) == 0);
            bool take = keepMin ? (ok < key) : (ok > key);
            if (take) { key = ok; val = ov; }
        }
        for (; j >= 1; j >>= 1) {
            float ok = __shfl_xor_sync(0xffffffffu, key, j);
            int   ov = __shfl_xor_sync(0xffffffffu, val, j);
            bool keepMin = ((tid & k) == 0) == ((tid & j) == 0);
            bool take = keepMin ? (ok < key) : (ok > key);
            if (take) { key = ok; val = ov; }
        }
    }
    s.sdp[tid] = key; s.perm[tid] = val;
    __syncthreads();

    float dmax = s.sdp[511];
    float pv = __expf(key - dmax);
    float qv = __expf(ALPHA_ * (key - dmax));
    s.p2[tid] = pack2(pv, pv);
    s.q2[tid] = pack2(qv, qv);

    // exact inclusive scalar scans of p, q over 512
    float ip = pv, iq = qv;
#pragma unroll
    for (int off = 1; off < 32; off <<= 1) {
        float np = __shfl_up_sync(0xffffffffu, ip, off);
        float nq = __shfl_up_sync(0xffffffffu, iq, off);
        if (lane >= off) { ip += np; iq += nq; }
    }
    if (lane == 31) { s.wtP[wid] = ip; s.wtQ[wid] = iq; }
    __syncthreads();
    float offP = 0.f, offQ = 0.f;
    for (int w2 = 0; w2 < wid; w2++) { offP += s.wtP[w2]; offQ += s.wtQ[w2]; }
    s.Pp[tid] = ip + offP;
    s.Pq[tid] = iq + offQ;

    // split point k_i = upper_bound(sdp, -s_i)
    {
        float ky = -s.ss[tid];
        int lo = 0, hi = 512;
        while (lo < hi) { int mid = (lo+hi) >> 1; if (s.sdp[mid] <= ky) lo = mid+1; else hi = mid; }
        s.kq[tid] = lo;
    }

    // gather permuted Wh rows as half2 channel pairs
    for (int j = wid; j < 512; j += 16) {
        float2 v = *(const float2*)&WhG[(size_t)s.perm[j]*64 + 2*lane];
        s.Whp[j*32 + lane] = __floats2half2_rn(v.x, v.y);
    }
    __syncthreads();

    // chunk sums (chunk = 16): warp w does chunks 2w, 2w+1  -> raw sums at cP2[c]
#pragma unroll
    for (int cc = 0; cc < 2; cc++) {
        int c = wid*2 + cc;
        ull aP = 0ull, aQ = 0ull;
#pragma unroll
        for (int t = 0; t < 16; t++) {
            int row = c*16 + t;
            float2 wf = __half22float2(s.Whp[row*32 + lane]);
            ull w2 = pack2(wf.x, wf.y);
            aP = ffma2(w2, s.p2[row], aP);
            aQ = ffma2(w2, s.q2[row], aQ);
        }
        s.cP2[c*32 + lane] = aP;
        s.cQ2[c*32 + lane] = aQ;
    }
    __syncthreads();

    // parallel inclusive Hillis-Steele scan over 32 chunks (1024 entries/array)
    int e0 = tid, e1 = tid + 512;
    int c0e = e0 >> 5, c1e = e1 >> 5;
#pragma unroll
    for (int d = 1; d < 32; d <<= 1) {
        ull v0P = s.cP2[e0], v1P = s.cP2[e1];
        ull v0Q = s.cQ2[e0], v1Q = s.cQ2[e1];
        ull a0P = (c0e >= d) ? s.cP2[e0 - 32*d] : 0ull;
        ull a1P = (c1e >= d) ? s.cP2[e1 - 32*d] : 0ull;
        ull a0Q = (c0e >= d) ? s.cQ2[e0 - 32*d] : 0ull;
        ull a1Q = (c1e >= d) ? s.cQ2[e1 - 32*d] : 0ull;
        __syncthreads();
        s.cP2[e0] = add2(v0P, a0P); s.cP2[e1] = add2(v1P, a1P);
        s.cQ2[e0] = add2(v0Q, a0Q); s.cQ2[e1] = add2(v1Q, a1Q);
        __syncthreads();
    }
    // shift inclusive -> exclusive ([c+1] = inc[c], [0] = 0, [32] = total)
    {
        ull i0P = s.cP2[e0], i1P = s.cP2[e1];
        ull i0Q = s.cQ2[e0], i1Q = s.cQ2[e1];
        __syncthreads();
        s.cP2[e0 + 32] = i0P; s.cP2[e1 + 32] = i1P;
        s.cQ2[e0 + 32] = i0Q; s.cQ2[e1 + 32] = i1Q;
        if (tid < 32) { s.cP2[tid] = 0ull; s.cQ2[tid] = 0ull; }
        __syncthreads();
    }

    float totS = s.Pp[511];
    float totPx, totPy; unpack2(s.cP2[32*32 + lane], totPx, totPy);
    float* outRow = out + (size_t)b*outBatch + (size_t)h*outHead;

    for (int it = 0; it < 32; it++) {
        int i = it*16 + wid;
        int kk = s.kq[i];
        float sv = s.ss[i];
        int c = kk >> 4, r = kk & 15;
        bool fwd = (r <= 8);
        int cb = fwd ? c : (c + 1);
        ull exP = s.cP2[cb*32 + lane], exQ = s.cQ2[cb*32 + lane];
        int t0 = fwd ? (c << 4) : kk;
        int t1 = fwd ? kk : ((c + 1) << 4);
        ull aP = 0ull, aQ = 0ull;
        for (int t = t0; t < t1; t++) {           // uniform across warp
            float2 wf = __half22float2(s.Whp[t*32 + lane]);
            ull w2 = pack2(wf.x, wf.y);
            aP = ffma2(w2, s.p2[t], aP);
            aQ = ffma2(w2, s.q2[t], aQ);
        }
        float sign = fwd ? 1.f : -1.f;
        float exPx, exPy, exQx, exQy, aPx, aPy, aQx, aQy;
        unpack2(exP, exPx, exPy); unpack2(exQ, exQx, exQy);
        unpack2(aP, aPx, aPy);   unpack2(aQ, aQx, aQy);
        float vPx = fmaf(sign, aPx, exPx), vPy = fmaf(sign, aPy, exPy);
        float vQx = fmaf(sign, aQx, exQx), vQy = fmaf(sign, aQy, exQy);

        float spx = kk ? s.Pp[kk-1] : 0.f;
        float sqx = kk ? s.Pq[kk-1] : 0.f;
        float spd = sv + dmax;
        float m   = spd > 0.f ? spd : ALPHA_*spd;
        float Af  = __expf(spd - m);
        float Bf  = __expf(ALPHA_*spd - m);
        float invZ = 1.f / (Af*(totS - spx) + Bf*sqx);
        float vx = (Af*(totPx - vPx) + Bf*vQx) * invZ;
        float vy = (Af*(totPy - vPy) + Bf*vQy) * invZ;
        if (applyElu) {
            vx = vx > 0.f ? vx : (__expf(vx) - 1.f);
            vy = vy > 0.f ? vy : (__expf(vy) - 1.f);
        }
        *(float2*)&outRow[(size_t)i*rowStride + 2*lane] = make_float2(vx, vy);
    }
}

// =====================================================================
// fc1 split-K, W staged through smem (kills 8x redundant L2 traffic)
// =====================================================================
__global__ void fc1_kernel(const float* __restrict__ W)
{
    __shared__ float z_s[32*40];
    __shared__ float w_s[32*64];      // [k2][col], 8 KB per kk-chunk
    int tid = threadIdx.x;       // 256
    int cb = blockIdx.x;         // 0..3
    int ks = blockIdx.y;         // 0..31
    int rg = tid >> 5;           // rows rg*4..+3
    int cl = tid & 31;
    int c0 = cl*2;               // local col in [0,64)
    int kbase = ks*1024;

    ull a0[4], a1[4];
#pragma unroll
    for (int i = 0; i < 4; i++) { a0[i] = 0ull; a1[i] = 0ull; }

    for (int kk = 0; kk < 1024; kk += 32) {
#pragma unroll
        for (int t = 0; t < 4; t++) {
            int lin = t*256 + tid;
            int row = lin >> 5, k2 = lin & 31;
            z_s[row*40 + k2] = g_h2[(size_t)row*32768 + kbase + kk + k2];
        }
#pragma unroll
        for (int t = 0; t < 8; t++) {
            int lin = t*256 + tid;
            int k2 = lin >> 6, o = lin & 63;
            w_s[k2*64 + o] = W[(size_t)(kbase + kk + k2)*256 + cb*64 + o];
        }
        __syncthreads();
#pragma unroll 2
        for (int kq = 0; kq < 8; kq++) {
            float2 w0 = *(const float2*)&w_s[(4*kq+0)*64 + c0];
            float2 w1 = *(const float2*)&w_s[(4*kq+1)*64 + c0];
            float2 w2 = *(const float2*)&w_s[(4*kq+2)*64 + c0];
            float2 w3 = *(const float2*)&w_s[(4*kq+3)*64 + c0];
            ull wa0 = pack2(w0.x, w1.x), wa1 = pack2(w2.x, w3.x);
            ull wb0 = pack2(w0.y, w1.y), wb1 = pack2(w2.y, w3.y);
#pragma unroll
            for (int i = 0; i < 4; i++) {
                ulonglong2 zz = *(const ulonglong2*)&z_s[(rg*4+i)*40 + 4*kq];
                a0[i] = ffma2(zz.x, wa0, a0[i]);
                a1[i] = ffma2(zz.x, wb0, a1[i]);
                a0[i] = ffma2(zz.y, wa1, a0[i]);
                a1[i] = ffma2(zz.y, wb1, a1[i]);
            }
        }
        __syncthreads();
    }
#pragma unroll
    for (int i = 0; i < 4; i++) {
        g_z1p[(size_t)ks*8192 + (rg*4+i)*256 + cb*64 + c0    ] = pair_sum(a0[i]);
        g_z1p[(size_t)ks*8192 + (rg*4+i)*256 + cb*64 + c0 + 1] = pair_sum(a1[i]);
    }
}

// =====================================================================
// head: reduce fc1 partials + relu -> fc2 relu -> fc3 tanh (fc3 parallel)
// =====================================================================
__global__ void head_kernel(const float* __restrict__ fc1_b,
                            const float* __restrict__ fc2_w,
                            const float* __restrict__ fc2_b,
                            const float* __restrict__ fc3_w,
                            const float* __restrict__ fc3_b,
                            float* __restrict__ out)
{
    __shared__ float z2[256], z3[256], red[256];
    int b = blockIdx.x, t = threadIdx.x;
    float v = fc1_b[t];
#pragma unroll
    for (int ks = 0; ks < 32; ks++) v += g_z1p[(size_t)ks*8192 + b*256 + t];
    z2[t] = v > 0.f ? v : 0.f;
    __syncthreads();
    float y = fc2_b[t];
#pragma unroll 8
    for (int k = 0; k < 256; k++) y += z2[k] * fc2_w[(size_t)k*256 + t];
    z3[t] = y > 0.f ? y : 0.f;
    __syncthreads();
    // fc3: t -> (act = t&3, group = t>>2), 4 k each, then reduce
    {
        int act = t & 3, grp = t >> 2;
        float partial = 0.f;
#pragma unroll
        for (int u = 0; u < 4; u++) {
            int k = grp*4 + u;
            partial += z3[k] * fc3_w[k*ACT_ + act];
        }
        red[t] = partial;
    }
    __syncthreads();
    if (t < ACT_) {
        float a = fc3_b[t];
#pragma unroll
        for (int j = 0; j < 64; j++) a += red[j*4 + t];
        out[b*ACT_ + t] = tanhf(a);
    }
}

// =====================================================================
extern "C" void kernel_launch(void* const* d_in, const int* in_sizes, int n_in,
                              void* d_out, int out_size)
{
    (void)in_sizes; (void)n_in; (void)out_size;
    const float* state     = (const float*)d_in[0];
    const float* W_heads   = (const float*)d_in[1];
    const float* a_src     = (const float*)d_in[2];
    const float* a_dst     = (const float*)d_in[3];
    const float* W_out     = (const float*)d_in[4];
    const float* a_out_src = (const float*)d_in[5];
    const float* a_out_dst = (const float*)d_in[6];
    const float* fc1_w     = (const float*)d_in[7];
    const float* fc1_b     = (const float*)d_in[8];
    const float* fc2_w     = (const float*)d_in[9];
    const float* fc2_b     = (const float*)d_in[10];
    const float* fc3_w     = (const float*)d_in[11];
    const float* fc3_b     = (const float*)d_in[12];
    float* out = (float*)d_out;

    float *pWh, *pss, *psd, *px, *pWh2, *ps2s, *ps2d, *ph2;
    cudaGetSymbolAddress((void**)&pWh,  g_Wh);
    cudaGetSymbolAddress((void**)&pss,  g_ssrc);
    cudaGetSymbolAddress((void**)&psd,  g_sdst);
    cudaGetSymbolAddress((void**)&px,   g_x);
    cudaGetSymbolAddress((void**)&pWh2, g_Wh2);
    cudaGetSymbolAddress((void**)&ps2s, g_s2s);
    cudaGetSymbolAddress((void**)&ps2d, g_s2d);
    cudaGetSymbolAddress((void**)&ph2,  g_h2);

    int attSmem = (int)sizeof(AttSmem);
    cudaFuncSetAttribute(attend_kernel, cudaFuncAttributeMaxDynamicSharedMemorySize, attSmem);

    gemm_s_kernel<<<dim3(128, 8), 256>>>(state, W_heads, a_src, a_dst,
                                         pWh, pss, psd,
                                         64, H_*N_*64, N_*64, H_*N_);
    attend_kernel<<<256, 512, attSmem>>>(pWh, pss, psd, px,
                                         N_*H_*64, 64, H_*64, H_, 1);
    gemm_s_kernel<<<dim3(128, 1), 256>>>(px, W_out, a_out_src, a_out_dst,
                                         pWh2, ps2s, ps2d,
                                         512, N_*64, 0, N_);
    attend_kernel<<<32, 512, attSmem>>>(pWh2, ps2s, ps2d, ph2,
                                        N_*64, 0, 64, 1, 0);
    fc1_kernel<<<dim3(4, 32), 256>>>(fc1_w);
    head_kernel<<<32, 256>>>(fc1_b, fc2_w, fc2_b, fc3_w, fc3_b, out);
}

// round 11
// speedup vs baseline: 2.0259x; 1.0565x over previous
#include <cuda_runtime.h>
#include <cuda_fp16.h>
#include <math.h>

#define B_    32
#define N_    512
#define H_    8
#define ACT_  4
#define ALPHA_ 0.2f

typedef unsigned long long ull;

// ---- packed f32x2 helpers (sm_100+) ----
__device__ __forceinline__ ull ffma2(ull a, ull b, ull c) {
    ull d; asm("fma.rn.f32x2 %0, %1, %2, %3;" : "=l"(d) : "l"(a), "l"(b), "l"(c)); return d;
}
__device__ __forceinline__ ull add2(ull a, ull b) {
    ull d; asm("add.rn.f32x2 %0, %1, %2;" : "=l"(d) : "l"(a), "l"(b)); return d;
}
__device__ __forceinline__ ull pack2(float lo, float hi) {
    ull r; asm("mov.b64 %0, {%1,%2};" : "=l"(r) : "f"(lo), "f"(hi)); return r;
}
__device__ __forceinline__ void unpack2(ull v, float& lo, float& hi) {
    asm("mov.b64 {%0,%1}, %2;" : "=f"(lo), "=f"(hi) : "l"(v));
}
__device__ __forceinline__ float pair_sum(ull v) {
    float lo, hi; unpack2(v, lo, hi); return lo + hi;
}

// ---------------- device scratch ----------------
__device__ float g_Wh  [B_*H_*N_*64];
__device__ float g_ssrc[B_*H_*N_];
__device__ float g_sdst[B_*H_*N_];
__device__ float g_x   [B_*N_*H_*64];
__device__ float g_Wh2 [B_*N_*64];
__device__ float g_s2s [B_*N_];
__device__ float g_s2d [B_*N_];
__device__ float g_h2  [B_*N_*64];
__device__ float g_z1p [32*B_*256];

// =====================================================================
// GEMM (16*RPT)-row x 64-col tile, LDS.128 k-quads + ffma2,
// + per-row dots with aSrc/aDst.
// =====================================================================
template<int RPT>
__global__ void gemm_s_kernel(const float* __restrict__ A,
                              const float* __restrict__ Ball,
                              const float* __restrict__ aSrc,
                              const float* __restrict__ aDst,
                              float* __restrict__ Cout,
                              float* __restrict__ sSrc,
                              float* __restrict__ sDst,
                              int K, int outBatch, int outHead, int sBatch)
{
    constexpr int ROWS = 16*RPT;
    __shared__ float As[ROWS*64];
    __shared__ float Bst[64*68];

    int tid = threadIdx.x;            // 256
    int r0  = blockIdx.x * ROWS;
    int h   = blockIdx.y;
    int b   = r0 / N_;
    int n0  = r0 % N_;
    const float* Bmat = Ball + (size_t)h*K*64;

    int tr = tid >> 4;                // 0..15 -> rows tr*RPT..+RPT-1
    int tc = tid & 15;                // cols tc, tc+16, tc+32, tc+48

    ull acc[RPT][4];
#pragma unroll
    for (int i = 0; i < RPT; i++)
#pragma unroll
        for (int j = 0; j < 4; j++) acc[i][j] = 0ull;

    for (int k0 = 0; k0 < K; k0 += 64) {
#pragma unroll
        for (int t = 0; t < RPT*4; t++) {
            int lin = t*256 + tid;
            int row = lin >> 6, kk = lin & 63;
            As[row*64 + kk] = A[(size_t)(r0+row)*K + k0 + kk];
        }
#pragma unroll
        for (int t = 0; t < 16; t++) {
            int lin = t*256 + tid;
            int kk = lin >> 6, o = lin & 63;
            Bst[o*68 + kk] = Bmat[(size_t)(k0+kk)*64 + o];
        }
        __syncthreads();
#pragma unroll 2
        for (int kq = 0; kq < 16; kq++) {
            ulonglong2 b0 = *(const ulonglong2*)&Bst[(tc     )*68 + 4*kq];
            ulonglong2 b1 = *(const ulonglong2*)&Bst[(tc + 16)*68 + 4*kq];
            ulonglong2 b2 = *(const ulonglong2*)&Bst[(tc + 32)*68 + 4*kq];
            ulonglong2 b3 = *(const ulonglong2*)&Bst[(tc + 48)*68 + 4*kq];
#pragma unroll
            for (int i = 0; i < RPT; i++) {
                ulonglong2 av = *(const ulonglong2*)&As[(tr*RPT+i)*64 + 4*kq];
                acc[i][0] = ffma2(av.x, b0.x, acc[i][0]);
                acc[i][1] = ffma2(av.x, b1.x, acc[i][1]);
                acc[i][2] = ffma2(av.x, b2.x, acc[i][2]);
                acc[i][3] = ffma2(av.x, b3.x, acc[i][3]);
                acc[i][0] = ffma2(av.y, b0.y, acc[i][0]);
                acc[i][1] = ffma2(av.y, b1.y, acc[i][1]);
                acc[i][2] = ffma2(av.y, b2.y, acc[i][2]);
                acc[i][3] = ffma2(av.y, b3.y, acc[i][3]);
            }
        }
        __syncthreads();
    }

    float c[RPT][4];
#pragma unroll
    for (int i = 0; i < RPT; i++)
#pragma unroll
        for (int j = 0; j < 4; j++) c[i][j] = pair_sum(acc[i][j]);

    float* outP = Cout + (size_t)b*outBatch + (size_t)h*outHead + (size_t)n0*64;
#pragma unroll
    for (int i = 0; i < RPT; i++) {
        int row = tr*RPT + i;
        outP[(size_t)row*64 + tc     ] = c[i][0];
        outP[(size_t)row*64 + tc + 16] = c[i][1];
        outP[(size_t)row*64 + tc + 32] = c[i][2];
        outP[(size_t)row*64 + tc + 48] = c[i][3];
    }

    const float* aS = aSrc + (size_t)h*64;
    const float* aD = aDst + (size_t)h*64;
    float aSv[4], aDv[4];
#pragma unroll
    for (int j = 0; j < 4; j++) {
        aSv[j] = __ldg(&aS[tc + 16*j]);
        aDv[j] = __ldg(&aD[tc + 16*j]);
    }
#pragma unroll
    for (int i = 0; i < RPT; i++) {
        float ss = c[i][0]*aSv[0] + c[i][1]*aSv[1] + c[i][2]*aSv[2] + c[i][3]*aSv[3];
        float sd = c[i][0]*aDv[0] + c[i][1]*aDv[1] + c[i][2]*aDv[2] + c[i][3]*aDv[3];
#pragma unroll
        for (int off = 8; off > 0; off >>= 1) {
            ss += __shfl_down_sync(0xffffffffu, ss, off, 16);
            sd += __shfl_down_sync(0xffffffffu, sd, off, 16);
        }
        if (tc == 0) {
            int n = n0 + tr*RPT + i;
            sSrc[(size_t)b*sBatch + (size_t)h*N_ + n] = ss;
            sDst[(size_t)b*sBatch + (size_t)h*N_ + n] = sd;
        }
    }
}

// =====================================================================
// Sorted-prefix GAT attend v5: v4 + query-split (qSplit blocks per group).
// Preamble (sort/scan/gather/chunk prefix) replicated per block;
// output queries divided qSplit ways.
// =====================================================================
struct AttSmem {
    __half2 Whp[512*32];               // 64 KB
    ull p2[512], q2[512];              // 8 KB
    ull cP2[33*32], cQ2[33*32];        // 16.5 KB, exclusive chunk prefix, [32]=total
    float sdp[512], ss[512], Pp[512], Pq[512];
    int   perm[512], kq[512];
    float wtP[16], wtQ[16];
};

__global__ void attend_kernel(const float* __restrict__ Wh,
                              const float* __restrict__ sS,
                              const float* __restrict__ sD,
                              float* __restrict__ out,
                              int outBatch, int outHead, int rowStride,
                              int hPerB, int applyElu, int qSplit)
{
    extern __shared__ char smraw[];
    AttSmem& s = *reinterpret_cast<AttSmem*>(smraw);
    int tid  = threadIdx.x;            // 512
    int lane = tid & 31, wid = tid >> 5;   // 16 warps
    int g  = blockIdx.x / qSplit;
    int qo = blockIdx.x % qSplit;
    int b = g / hPerB, h = g % hPerB;
    const float* WhG = Wh + (size_t)g*512*64;

    float key = sD[(size_t)g*512 + tid];
    int   val = tid;
    s.ss[tid] = sS[(size_t)g*512 + tid];

    // ---- bitonic sort ascending: smem for j>=32, shfl for j<=16 ----
    for (int k = 2; k <= 512; k <<= 1) {
        int j = k >> 1;
        for (; j >= 32; j >>= 1) {
            s.sdp[tid] = key; s.perm[tid] = val;
            __syncthreads();
            float ok = s.sdp[tid ^ j];
            int   ov = s.perm[tid ^ j];
            __syncthreads();
            bool keepMin = ((tid & k) == 0) == ((tid & j) == 0);
            bool take = keepMin ? (ok < key) : (ok > key);
            if (take) { key = ok; val = ov; }
        }
        for (; j >= 1; j >>= 1) {
            float ok = __shfl_xor_sync(0xffffffffu, key, j);
            int   ov = __shfl_xor_sync(0xffffffffu, val, j);
            bool keepMin = ((tid & k) == 0) == ((tid & j) == 0);
            bool take = keepMin ? (ok < key) : (ok > key);
            if (take) { key = ok; val = ov; }
        }
    }
    s.sdp[tid] = key; s.perm[tid] = val;
    __syncthreads();

    float dmax = s.sdp[511];
    float pv = __expf(key - dmax);
    float qv = __expf(ALPHA_ * (key - dmax));
    s.p2[tid] = pack2(pv, pv);
    s.q2[tid] = pack2(qv, qv);

    // exact inclusive scalar scans of p, q over 512
    float ip = pv, iq = qv;
#pragma unroll
    for (int off = 1; off < 32; off <<= 1) {
        float np = __shfl_up_sync(0xffffffffu, ip, off);
        float nq = __shfl_up_sync(0xffffffffu, iq, off);
        if (lane >= off) { ip += np; iq += nq; }
    }
    if (lane == 31) { s.wtP[wid] = ip; s.wtQ[wid] = iq; }
    __syncthreads();
    float offP = 0.f, offQ = 0.f;
    for (int w2 = 0; w2 < wid; w2++) { offP += s.wtP[w2]; offQ += s.wtQ[w2]; }
    s.Pp[tid] = ip + offP;
    s.Pq[tid] = iq + offQ;

    // split point k_i = upper_bound(sdp, -s_i)
    {
        float ky = -s.ss[tid];
        int lo = 0, hi = 512;
        while (lo < hi) { int mid = (lo+hi) >> 1; if (s.sdp[mid] <= ky) lo = mid+1; else hi = mid; }
        s.kq[tid] = lo;
    }

    // gather permuted Wh rows as half2 channel pairs
    for (int j = wid; j < 512; j += 16) {
        float2 v = *(const float2*)&WhG[(size_t)s.perm[j]*64 + 2*lane];
        s.Whp[j*32 + lane] = __floats2half2_rn(v.x, v.y);
    }
    __syncthreads();

    // chunk sums (chunk = 16): warp w does chunks 2w, 2w+1
#pragma unroll
    for (int cc = 0; cc < 2; cc++) {
        int c = wid*2 + cc;
        ull aP = 0ull, aQ = 0ull;
#pragma unroll
        for (int t = 0; t < 16; t++) {
            int row = c*16 + t;
            float2 wf = __half22float2(s.Whp[row*32 + lane]);
            ull w2 = pack2(wf.x, wf.y);
            aP = ffma2(w2, s.p2[row], aP);
            aQ = ffma2(w2, s.q2[row], aQ);
        }
        s.cP2[c*32 + lane] = aP;
        s.cQ2[c*32 + lane] = aQ;
    }
    __syncthreads();

    // parallel inclusive Hillis-Steele scan over 32 chunks
    int e0 = tid, e1 = tid + 512;
    int c0e = e0 >> 5, c1e = e1 >> 5;
#pragma unroll
    for (int d = 1; d < 32; d <<= 1) {
        ull v0P = s.cP2[e0], v1P = s.cP2[e1];
        ull v0Q = s.cQ2[e0], v1Q = s.cQ2[e1];
        ull a0P = (c0e >= d) ? s.cP2[e0 - 32*d] : 0ull;
        ull a1P = (c1e >= d) ? s.cP2[e1 - 32*d] : 0ull;
        ull a0Q = (c0e >= d) ? s.cQ2[e0 - 32*d] : 0ull;
        ull a1Q = (c1e >= d) ? s.cQ2[e1 - 32*d] : 0ull;
        __syncthreads();
        s.cP2[e0] = add2(v0P, a0P); s.cP2[e1] = add2(v1P, a1P);
        s.cQ2[e0] = add2(v0Q, a0Q); s.cQ2[e1] = add2(v1Q, a1Q);
        __syncthreads();
    }
    // shift inclusive -> exclusive ([c+1] = inc[c], [0] = 0, [32] = total)
    {
        ull i0P = s.cP2[e0], i1P = s.cP2[e1];
        ull i0Q = s.cQ2[e0], i1Q = s.cQ2[e1];
        __syncthreads();
        s.cP2[e0 + 32] = i0P; s.cP2[e1 + 32] = i1P;
        s.cQ2[e0 + 32] = i0Q; s.cQ2[e1 + 32] = i1Q;
        if (tid < 32) { s.cP2[tid] = 0ull; s.cQ2[tid] = 0ull; }
        __syncthreads();
    }

    float totS = s.Pp[511];
    float totPx, totPy; unpack2(s.cP2[32*32 + lane], totPx, totPy);
    float* outRow = out + (size_t)b*outBatch + (size_t)h*outHead;

    int qLen = 512 / qSplit;
    int itCount = qLen / 16;
    int qBase = qo * qLen;
    for (int it = 0; it < itCount; it++) {
        int i = qBase + it*16 + wid;
        int kk = s.kq[i];
        float sv = s.ss[i];
        int c = kk >> 4, r = kk & 15;
        bool fwd = (r <= 8);
        int cb = fwd ? c : (c + 1);
        ull exP = s.cP2[cb*32 + lane], exQ = s.cQ2[cb*32 + lane];
        int t0 = fwd ? (c << 4) : kk;
        int t1 = fwd ? kk : ((c + 1) << 4);
        ull aP = 0ull, aQ = 0ull;
        for (int t = t0; t < t1; t++) {           // uniform across warp
            float2 wf = __half22float2(s.Whp[t*32 + lane]);
            ull w2 = pack2(wf.x, wf.y);
            aP = ffma2(w2, s.p2[t], aP);
            aQ = ffma2(w2, s.q2[t], aQ);
        }
        float sign = fwd ? 1.f : -1.f;
        float exPx, exPy, exQx, exQy, aPx, aPy, aQx, aQy;
        unpack2(exP, exPx, exPy); unpack2(exQ, exQx, exQy);
        unpack2(aP, aPx, aPy);   unpack2(aQ, aQx, aQy);
        float vPx = fmaf(sign, aPx, exPx), vPy = fmaf(sign, aPy, exPy);
        float vQx = fmaf(sign, aQx, exQx), vQy = fmaf(sign, aQy, exQy);

        float spx = kk ? s.Pp[kk-1] : 0.f;
        float sqx = kk ? s.Pq[kk-1] : 0.f;
        float spd = sv + dmax;
        float m   = spd > 0.f ? spd : ALPHA_*spd;
        float Af  = __expf(spd - m);
        float Bf  = __expf(ALPHA_*spd - m);
        float invZ = 1.f / (Af*(totS - spx) + Bf*sqx);
        float vx = (Af*(totPx - vPx) + Bf*vQx) * invZ;
        float vy = (Af*(totPy - vPy) + Bf*vQy) * invZ;
        if (applyElu) {
            vx = vx > 0.f ? vx : (__expf(vx) - 1.f);
            vy = vy > 0.f ? vy : (__expf(vy) - 1.f);
        }
        *(float2*)&outRow[(size_t)i*rowStride + 2*lane] = make_float2(vx, vy);
    }
}

// =====================================================================
// fc1 split-K, W staged through smem
// =====================================================================
__global__ void fc1_kernel(const float* __restrict__ W)
{
    __shared__ float z_s[32*40];
    __shared__ float w_s[32*64];
    int tid = threadIdx.x;       // 256
    int cb = blockIdx.x;         // 0..3
    int ks = blockIdx.y;         // 0..31
    int rg = tid >> 5;
    int cl = tid & 31;
    int c0 = cl*2;
    int kbase = ks*1024;

    ull a0[4], a1[4];
#pragma unroll
    for (int i = 0; i < 4; i++) { a0[i] = 0ull; a1[i] = 0ull; }

    for (int kk = 0; kk < 1024; kk += 32) {
#pragma unroll
        for (int t = 0; t < 4; t++) {
            int lin = t*256 + tid;
            int row = lin >> 5, k2 = lin & 31;
            z_s[row*40 + k2] = g_h2[(size_t)row*32768 + kbase + kk + k2];
        }
#pragma unroll
        for (int t = 0; t < 8; t++) {
            int lin = t*256 + tid;
            int k2 = lin >> 6, o = lin & 63;
            w_s[k2*64 + o] = W[(size_t)(kbase + kk + k2)*256 + cb*64 + o];
        }
        __syncthreads();
#pragma unroll 2
        for (int kq = 0; kq < 8; kq++) {
            float2 w0 = *(const float2*)&w_s[(4*kq+0)*64 + c0];
            float2 w1 = *(const float2*)&w_s[(4*kq+1)*64 + c0];
            float2 w2 = *(const float2*)&w_s[(4*kq+2)*64 + c0];
            float2 w3 = *(const float2*)&w_s[(4*kq+3)*64 + c0];
            ull wa0 = pack2(w0.x, w1.x), wa1 = pack2(w2.x, w3.x);
            ull wb0 = pack2(w0.y, w1.y), wb1 = pack2(w2.y, w3.y);
#pragma unroll
            for (int i = 0; i < 4; i++) {
                ulonglong2 zz = *(const ulonglong2*)&z_s[(rg*4+i)*40 + 4*kq];
                a0[i] = ffma2(zz.x, wa0, a0[i]);
                a1[i] = ffma2(zz.x, wb0, a1[i]);
                a0[i] = ffma2(zz.y, wa1, a0[i]);
                a1[i] = ffma2(zz.y, wb1, a1[i]);
            }
        }
        __syncthreads();
    }
#pragma unroll
    for (int i = 0; i < 4; i++) {
        g_z1p[(size_t)ks*8192 + (rg*4+i)*256 + cb*64 + c0    ] = pair_sum(a0[i]);
        g_z1p[(size_t)ks*8192 + (rg*4+i)*256 + cb*64 + c0 + 1] = pair_sum(a1[i]);
    }
}

// =====================================================================
// head: reduce fc1 partials + relu -> fc2 relu -> fc3 tanh
// =====================================================================
__global__ void head_kernel(const float* __restrict__ fc1_b,
                            const float* __restrict__ fc2_w,
                            const float* __restrict__ fc2_b,
                            const float* __restrict__ fc3_w,
                            const float* __restrict__ fc3_b,
                            float* __restrict__ out)
{
    __shared__ float z2[256], z3[256], red[256];
    int b = blockIdx.x, t = threadIdx.x;
    float v = fc1_b[t];
#pragma unroll
    for (int ks = 0; ks < 32; ks++) v += g_z1p[(size_t)ks*8192 + b*256 + t];
    z2[t] = v > 0.f ? v : 0.f;
    __syncthreads();
    float y = fc2_b[t];
#pragma unroll 8
    for (int k = 0; k < 256; k++) y += z2[k] * fc2_w[(size_t)k*256 + t];
    z3[t] = y > 0.f ? y : 0.f;
    __syncthreads();
    {
        int act = t & 3, grp = t >> 2;
        float partial = 0.f;
#pragma unroll
        for (int u = 0; u < 4; u++) {
            int k = grp*4 + u;
            partial += z3[k] * fc3_w[k*ACT_ + act];
        }
        red[t] = partial;
    }
    __syncthreads();
    if (t < ACT_) {
        float a = fc3_b[t];
#pragma unroll
        for (int j = 0; j < 64; j++) a += red[j*4 + t];
        out[b*ACT_ + t] = tanhf(a);
    }
}

// =====================================================================
extern "C" void kernel_launch(void* const* d_in, const int* in_sizes, int n_in,
                              void* d_out, int out_size)
{
    (void)in_sizes; (void)n_in; (void)out_size;
    const float* state     = (const float*)d_in[0];
    const float* W_heads   = (const float*)d_in[1];
    const float* a_src     = (const float*)d_in[2];
    const float* a_dst     = (const float*)d_in[3];
    const float* W_out     = (const float*)d_in[4];
    const float* a_out_src = (const float*)d_in[5];
    const float* a_out_dst = (const float*)d_in[6];
    const float* fc1_w     = (const float*)d_in[7];
    const float* fc1_b     = (const float*)d_in[8];
    const float* fc2_w     = (const float*)d_in[9];
    const float* fc2_b     = (const float*)d_in[10];
    const float* fc3_w     = (const float*)d_in[11];
    const float* fc3_b     = (const float*)d_in[12];
    float* out = (float*)d_out;

    float *pWh, *pss, *psd, *px, *pWh2, *ps2s, *ps2d, *ph2;
    cudaGetSymbolAddress((void**)&pWh,  g_Wh);
    cudaGetSymbolAddress((void**)&pss,  g_ssrc);
    cudaGetSymbolAddress((void**)&psd,  g_sdst);
    cudaGetSymbolAddress((void**)&px,   g_x);
    cudaGetSymbolAddress((void**)&pWh2, g_Wh2);
    cudaGetSymbolAddress((void**)&ps2s, g_s2s);
    cudaGetSymbolAddress((void**)&ps2d, g_s2d);
    cudaGetSymbolAddress((void**)&ph2,  g_h2);

    int attSmem = (int)sizeof(AttSmem);
    cudaFuncSetAttribute(attend_kernel, cudaFuncAttributeMaxDynamicSharedMemorySize, attSmem);

    // Layer 1 GEMM (128-row tiles): 1024 blocks
    gemm_s_kernel<8><<<dim3(128, 8), 256>>>(state, W_heads, a_src, a_dst,
                                            pWh, pss, psd,
                                            64, H_*N_*64, N_*64, H_*N_);
    // Attend 1 + ELU, one block per (b,h): grid 256 (2 blocks/SM, full chip)
    attend_kernel<<<256, 512, attSmem>>>(pWh, pss, psd, px,
                                         N_*H_*64, 64, H_*64, H_, 1, 1);
    // Layer 2 GEMM (64-row tiles): 256 blocks for better latency hiding
    gemm_s_kernel<4><<<dim3(256, 1), 256>>>(px, W_out, a_out_src, a_out_dst,
                                            pWh2, ps2s, ps2d,
                                            512, N_*64, 0, N_);
    // Attend 2, query-split 4-way: grid 128 (4x the SMs of before)
    attend_kernel<<<128, 512, attSmem>>>(pWh2, ps2s, ps2d, ph2,
                                         N_*64, 0, 64, 1, 0, 4);
    fc1_kernel<<<dim3(4, 32), 256>>>(fc1_w);
    head_kernel<<<32, 256>>>(fc1_b, fc2_w, fc2_b, fc3_w, fc3_b, out);
}